// round 9
// baseline (speedup 1.0000x reference)
#include <cuda_runtime.h>

// AdderConv + BatchNorm2d (training stats): x[8,32,28,28], W[64,32,3,3], pad=1.
// out[n,o,h,w] = -sum_k |x - w|, then per-channel BN (biased var, eps=1e-5).
//
// Kernel 0 (pad): x -> zero-haloed (x,x)-duplicated u64 scratch g_xpad[n][c][30][32];
//   also resets the global barrier counter (graph-replay safe).
// Kernel 1 (mega): grid (4 row-tiles 7x28, 16 oc-quads, 8 n) = 512 blocks x 224 thr,
//   ALL co-resident (launch_bounds(224,6), ~12KB smem). Full K=288 per block:
//   per k-iter: LDG.64 x + LDS.128 w(broadcast) + 2x(FADD2,2LOP3,FADD2) = 10 issues
//   per 4 elem-ops. Outputs held in registers. Block reduces per-oc sum/sumsq ->
//   g_psum/g_psumsq, software global barrier, per-oc scale/bias, in-register
//   normalize, single out write. No partial scratch, no combine kernel.

__device__ __align__(16) unsigned long long g_xpad[8 * 32 * 30 * 32 + 64]; // +slack
__device__ float g_psum[64 * 32];     // [oc][n*4+rt]
__device__ float g_psumsq[64 * 32];
__device__ unsigned g_ctr;

__device__ __forceinline__ void adder2(unsigned long long& acc,
                                       unsigned long long xx,
                                       unsigned long long w,
                                       unsigned long long mask) {
    asm("{\n\t"
        ".reg .b64 t;\n\t"
        "add.rn.f32x2 t, %1, %2;\n\t"
        "and.b64 t, t, %3;\n\t"
        "add.rn.f32x2 %0, %0, t;\n\t"
        "}"
        : "+l"(acc) : "l"(xx), "l"(w), "l"(mask));
}

// Kernel 0: build padded duplicated x. 240 blocks x 256 thr, 4 u64 each.
__global__ __launch_bounds__(256) void pad_kernel(const float* __restrict__ x)
{
    const int gid = blockIdx.x * 256 + threadIdx.x;        // 0..61439
    const int w0  = (gid * 4) & 31;
    const int rowid = gid >> 3;                            // 0..7679
    const int h  = rowid % 30;
    const int cn = rowid / 30;                             // n*32 + c
    unsigned long long* dst = g_xpad + ((size_t)cn * 30 + h) * 32 + w0;
    const float* src = x + ((size_t)cn * 28 + (h - 1)) * 28;
    #pragma unroll
    for (int j = 0; j < 4; ++j) {
        int w = w0 + j;
        float v = 0.f;
        if (h >= 1 && h <= 28 && w >= 1 && w <= 28) v = src[w - 1];
        unsigned u = __float_as_uint(v);
        dst[j] = ((unsigned long long)u << 32) | u;
    }
    if (gid == 0) g_ctr = 0;   // replay-safe reset for the global barrier
}

__global__ __launch_bounds__(224, 6) void mega_kernel(
    const float* __restrict__ W, const float* __restrict__ gamma,
    const float* __restrict__ beta, float* __restrict__ out)
{
    __shared__ __align__(16) ulonglong2 nws[288];   // 4.6KB: {(-w0,-w1),(-w2,-w3)} per k
    __shared__ float red[8][8];                     // warp partials: 8 vals x 7 warps
    __shared__ float2 scb[4];                       // per-oc {scale, bias}

    const int rt  = blockIdx.x;          // 0..3, rows rt*7 .. rt*7+6
    const int ocq = blockIdx.y;          // 0..15, ocs ocq*4 .. ocq*4+3
    const int n   = blockIdx.z;          // 0..7
    const int tid = threadIdx.x;
    const int wid = tid >> 5;            // 0..6
    const int lid = tid & 31;
    const int row = wid;                 // warp = output row in tile
    const int col = lid;                 // valid if < 28

    // Pack negated weights: nws[k] = { pack(-W[o0][k],-W[o1][k]), pack(-W[o2][k],-W[o3][k]) }
    const float* Wb = W + (ocq * 4) * 288;
    unsigned long long* nw64 = (unsigned long long*)nws;
    for (int i = tid; i < 576; i += 224) {
        int k = i >> 1, pr = i & 1;
        unsigned lo = __float_as_uint(-Wb[(2 * pr) * 288 + k]);
        unsigned hi = __float_as_uint(-Wb[(2 * pr + 1) * 288 + k]);
        nw64[k * 2 + pr] = ((unsigned long long)hi << 32) | lo;
    }
    __syncthreads();

    const unsigned long long mask = 0x7FFFFFFF7FFFFFFFULL;
    unsigned long long acc0 = 0ull, acc1 = 0ull;

    const unsigned long long* xp =
        g_xpad + (((size_t)(n * 32) * 30) + rt * 7 + row) * 32 + col;

    #pragma unroll 1
    for (int c = 0; c < 32; ++c) {
        const ulonglong2* wk = nws + c * 9;
        #pragma unroll
        for (int dr = 0; dr < 3; ++dr) {
            #pragma unroll
            for (int dq = 0; dq < 3; ++dq) {
                unsigned long long xx = xp[dr * 32 + dq];
                ulonglong2 w = wk[dr * 3 + dq];
                adder2(acc0, xx, w.x, mask);
                adder2(acc1, xx, w.y, mask);
            }
        }
        xp += 960;                       // next channel: 30*32 u64
    }

    // Final values (negate). Lanes 28..31 are invalid -> zero for stats.
    float v0 = -__uint_as_float((unsigned)(acc0 & 0xFFFFFFFFu));
    float v1 = -__uint_as_float((unsigned)(acc0 >> 32));
    float v2 = -__uint_as_float((unsigned)(acc1 & 0xFFFFFFFFu));
    float v3 = -__uint_as_float((unsigned)(acc1 >> 32));

    float s0 = v0, s1 = v1, s2 = v2, s3 = v3;
    float q0 = v0 * v0, q1 = v1 * v1, q2 = v2 * v2, q3 = v3 * v3;
    if (col >= 28) { s0 = s1 = s2 = s3 = 0.f; q0 = q1 = q2 = q3 = 0.f; }

    // Warp reduce 8 values, then fold 7 warps.
    #pragma unroll
    for (int d = 16; d > 0; d >>= 1) {
        s0 += __shfl_down_sync(0xFFFFFFFFu, s0, d);
        s1 += __shfl_down_sync(0xFFFFFFFFu, s1, d);
        s2 += __shfl_down_sync(0xFFFFFFFFu, s2, d);
        s3 += __shfl_down_sync(0xFFFFFFFFu, s3, d);
        q0 += __shfl_down_sync(0xFFFFFFFFu, q0, d);
        q1 += __shfl_down_sync(0xFFFFFFFFu, q1, d);
        q2 += __shfl_down_sync(0xFFFFFFFFu, q2, d);
        q3 += __shfl_down_sync(0xFFFFFFFFu, q3, d);
    }
    if (lid == 0) {
        red[0][wid] = s0; red[1][wid] = s1; red[2][wid] = s2; red[3][wid] = s3;
        red[4][wid] = q0; red[5][wid] = q1; red[6][wid] = q2; red[7][wid] = q3;
    }
    __syncthreads();

    const int pidx = n * 4 + rt;
    if (tid < 8) {
        float t = red[tid][0];
        #pragma unroll
        for (int u = 1; u < 7; ++u) t += red[tid][u];
        if (tid < 4) g_psum[(ocq * 4 + tid) * 32 + pidx] = t;
        else         g_psumsq[(ocq * 4 + (tid - 4)) * 32 + pidx] = t;
    }

    // Global barrier: all 512 blocks are co-resident.
    __syncthreads();
    if (tid == 0) {
        __threadfence();
        atomicAdd(&g_ctr, 1u);
        while (*(volatile unsigned*)&g_ctr < 512u) __nanosleep(64);
        __threadfence();
    }
    __syncthreads();

    // Per-oc stats: warps 0..3 each fold one oc's 32 partials.
    if (wid < 4) {
        const int oc = ocq * 4 + wid;
        float ss = *(volatile float*)&g_psum[oc * 32 + lid];
        float qq = *(volatile float*)&g_psumsq[oc * 32 + lid];
        #pragma unroll
        for (int d = 16; d > 0; d >>= 1) {
            ss += __shfl_down_sync(0xFFFFFFFFu, ss, d);
            qq += __shfl_down_sync(0xFFFFFFFFu, qq, d);
        }
        if (lid == 0) {
            float mean = ss * (1.f / 6272.f);
            float var  = qq * (1.f / 6272.f) - mean * mean;
            float sc = gamma[oc] * rsqrtf(var + 1e-5f);
            scb[wid] = make_float2(sc, beta[oc] - mean * sc);
        }
    }
    __syncthreads();

    if (col < 28) {
        float* ob = out + ((size_t)(n * 64 + ocq * 4)) * 784 + (rt * 7 + row) * 28 + col;
        float2 c0 = scb[0], c1 = scb[1], c2 = scb[2], c3 = scb[3];
        ob[0]       = v0 * c0.x + c0.y;
        ob[784]     = v1 * c1.x + c1.y;
        ob[2 * 784] = v2 * c2.x + c2.y;
        ob[3 * 784] = v3 * c3.x + c3.y;
    }
}

extern "C" void kernel_launch(void* const* d_in, const int* in_sizes, int n_in,
                              void* d_out, int out_size) {
    const float* x     = (const float*)d_in[0];  // [8,32,28,28]
    const float* W     = (const float*)d_in[1];  // [64,32,3,3]
    const float* gamma = (const float*)d_in[2];  // [64]
    const float* beta  = (const float*)d_in[3];  // [64]
    float* out = (float*)d_out;                  // [8,64,28,28]

    pad_kernel<<<240, 256>>>(x);
    dim3 g1(4, 16, 8);
    mega_kernel<<<g1, 224>>>(W, gamma, beta, out);
}

// round 10
// speedup vs baseline: 1.0923x; 1.0923x over previous
#include <cuda_runtime.h>

// AdderConv + BatchNorm2d (training stats): x[8,32,28,28], W[64,32,3,3], pad=1.
// out[n,o,h,w] = -sum_k |x - w|, then per-channel BN (biased var, eps=1e-5).
//
// Kernel 1: R1's measured-16us conv, verbatim. grid (4 spatial 14x14 tiles,
//   8 oc-groups of 8, 8 batch) x 256 thr, 41KB smem. Writes RAW adder output.
//   Block (0,0,0) resets the tail's barrier counter (graph-replay safe).
// Kernel 2: fused BN tail. 512 blocks x 256 thr (all co-resident): load own
//   (n,oc) row from out, block-reduce sum/sumsq -> g_psum/g_psumsq, software
//   global barrier, per-channel scale/bias, in-register normalize, write back.

__device__ float g_psum[512];     // per (n,oc)
__device__ float g_psumsq[512];
__device__ unsigned g_ctr;

__device__ __forceinline__ unsigned long long add_f32x2(unsigned long long a,
                                                        unsigned long long b) {
    unsigned long long r;
    asm("add.rn.f32x2 %0, %1, %2;" : "=l"(r) : "l"(a), "l"(b));
    return r;
}

// Kernel 1: adder conv (R1 structure, measured ~16us).
__global__ __launch_bounds__(256, 1) void adder_kernel(
    const float* __restrict__ x, const float* __restrict__ W, float* __restrict__ out)
{
    __shared__ __align__(16) float xs[32 * 16 * 16];
    __shared__ __align__(16) float nws[288 * 8];

    const int s   = blockIdx.x;   // spatial tile 0..3
    const int ocg = blockIdx.y;   // 0..7 (8 output channels each)
    const int n   = blockIdx.z;   // 0..7
    const int th  = (s >> 1) * 14;
    const int tw  = (s & 1) * 14;
    const int tid = threadIdx.x;

    if (tid == 0 && s == 0 && ocg == 0 && n == 0) g_ctr = 0;  // replay-safe reset

    // Load x tile (with zero halo for padding).
    const float* xb = x + n * (32 * 28 * 28);
    #pragma unroll
    for (int i = tid; i < 32 * 256; i += 256) {
        int c = i >> 8, cell = i & 255;
        int r = cell >> 4, col = cell & 15;
        int gh = th - 1 + r, gw = tw - 1 + col;
        float v = 0.f;
        if ((unsigned)gh < 28u && (unsigned)gw < 28u)
            v = xb[c * 784 + gh * 28 + gw];
        xs[i] = v;
    }
    // Load negated W slice, k-major so 8 oc values are contiguous per k.
    const float* Wb = W + ocg * (8 * 288);
    #pragma unroll
    for (int i = tid; i < 8 * 288; i += 256) {
        int o = i & 7, k = i >> 3;
        nws[k * 8 + o] = -Wb[o * 288 + k];
    }
    __syncthreads();

    if (tid < 196) {
        const int ph = tid / 14;
        const int pw = tid - ph * 14;
        unsigned long long acc0 = 0ull, acc1 = 0ull, acc2 = 0ull, acc3 = 0ull;
        const float* xp = xs + ph * 16 + pw;
        const ulonglong2* wp = (const ulonglong2*)nws;

        #pragma unroll 1
        for (int c = 0; c < 32; ++c) {
            const float* xc = xp + c * 256;
            #pragma unroll
            for (int r = 0; r < 3; ++r) {
                #pragma unroll
                for (int q = 0; q < 3; ++q) {
                    float xv = xc[r * 16 + q];
                    unsigned long long xx;
                    asm("mov.b64 %0, {%1, %1};" : "=l"(xx) : "r"(__float_as_uint(xv)));
                    const ulonglong2* w4 = wp + (c * 9 + r * 3 + q) * 2;
                    ulonglong2 wA = w4[0];
                    ulonglong2 wB = w4[1];
                    unsigned long long d0 = add_f32x2(xx, wA.x) & 0x7FFFFFFF7FFFFFFFULL;
                    unsigned long long d1 = add_f32x2(xx, wA.y) & 0x7FFFFFFF7FFFFFFFULL;
                    unsigned long long d2 = add_f32x2(xx, wB.x) & 0x7FFFFFFF7FFFFFFFULL;
                    unsigned long long d3 = add_f32x2(xx, wB.y) & 0x7FFFFFFF7FFFFFFFULL;
                    acc0 = add_f32x2(acc0, d0);
                    acc1 = add_f32x2(acc1, d1);
                    acc2 = add_f32x2(acc2, d2);
                    acc3 = add_f32x2(acc3, d3);
                }
            }
        }

        const int gh = th + ph, gw = tw + pw;
        float* ob = out + (n * 64 + ocg * 8) * 784 + gh * 28 + gw;
        unsigned long long a[4] = {acc0, acc1, acc2, acc3};
        #pragma unroll
        for (int j = 0; j < 4; ++j) {
            ob[(2 * j) * 784]     = -__uint_as_float((unsigned)(a[j] & 0xFFFFFFFFu));
            ob[(2 * j + 1) * 784] = -__uint_as_float((unsigned)(a[j] >> 32));
        }
    }
}

// Kernel 2: fused BN tail. 512 blocks x 256 thr, all co-resident.
__global__ __launch_bounds__(256) void tail_kernel(
    float* __restrict__ out, const float* __restrict__ gamma, const float* __restrict__ beta)
{
    __shared__ float rs[256], rq[256];
    __shared__ float sc_s, bi_s;

    const int bid = blockIdx.x;          // n*64 + oc
    const int oc  = bid & 63;
    const int tid = threadIdx.x;

    float4 v = make_float4(0.f, 0.f, 0.f, 0.f);
    float s = 0.f, sq = 0.f;
    if (tid < 196) {
        v = *(const float4*)(out + (size_t)bid * 784 + tid * 4);
        s  = v.x + v.y + v.z + v.w;
        sq = v.x * v.x + v.y * v.y + v.z * v.z + v.w * v.w;
    }
    rs[tid] = s; rq[tid] = sq;
    __syncthreads();
    #pragma unroll
    for (int st = 128; st > 0; st >>= 1) {
        if (tid < st) { rs[tid] += rs[tid + st]; rq[tid] += rq[tid + st]; }
        __syncthreads();
    }

    // Publish this (n,oc) partial; arrive at the global barrier; spin.
    if (tid == 0) {
        g_psum[bid] = rs[0];
        g_psumsq[bid] = rq[0];
        __threadfence();
        atomicAdd(&g_ctr, 1u);
        while (*(volatile unsigned*)&g_ctr < 512u) __nanosleep(64);
        __threadfence();
    }
    __syncthreads();

    // Per-channel stats: 8 lanes gather the 8 batch partials for this oc.
    if (tid < 8) {
        float ss = *(volatile float*)&g_psum[tid * 64 + oc];
        float qq = *(volatile float*)&g_psumsq[tid * 64 + oc];
        #pragma unroll
        for (int d = 4; d > 0; d >>= 1) {
            ss += __shfl_down_sync(0xFFu, ss, d, 8);
            qq += __shfl_down_sync(0xFFu, qq, d, 8);
        }
        if (tid == 0) {
            float mean = ss * (1.f / 6272.f);
            float var  = qq * (1.f / 6272.f) - mean * mean;
            float sc = gamma[oc] * rsqrtf(var + 1e-5f);
            sc_s = sc;
            bi_s = beta[oc] - mean * sc;
        }
    }
    __syncthreads();

    if (tid < 196) {
        const float sc = sc_s, bi = bi_s;
        v.x = v.x * sc + bi;
        v.y = v.y * sc + bi;
        v.z = v.z * sc + bi;
        v.w = v.w * sc + bi;
        *(float4*)(out + (size_t)bid * 784 + tid * 4) = v;
    }
}

extern "C" void kernel_launch(void* const* d_in, const int* in_sizes, int n_in,
                              void* d_out, int out_size) {
    const float* x     = (const float*)d_in[0];  // [8,32,28,28]
    const float* W     = (const float*)d_in[1];  // [64,32,3,3]
    const float* gamma = (const float*)d_in[2];  // [64]
    const float* beta  = (const float*)d_in[3];  // [64]
    float* out = (float*)d_out;                  // [8,64,28,28]

    dim3 g1(4, 8, 8);
    adder_kernel<<<g1, 256>>>(x, W, out);
    tail_kernel<<<512, 256>>>(out, gamma, beta);
}

// round 11
// speedup vs baseline: 1.2195x; 1.1165x over previous
#include <cuda_runtime.h>

// AdderConv + BatchNorm2d (training stats): x[8,32,28,28], W[64,32,3,3], pad=1.
// out[n,o,h,w] = -sum_k |x - w|, then per-channel BN (biased var, eps=1e-5).
//
// SINGLE fused kernel: R1's conv body (measured-fastest, unchanged) + in-register
// BN epilogue with a replay-safe ticket barrier across the 256 co-resident blocks
// (41KB smem -> 2 blocks/SM; 256 <= 148*2, proven resident by R4 occupancy data).
// No scratch round-trip, no tail kernel, no launch gaps.

__device__ float g_psum[64 * 32];     // [oc][pidx], pidx = n*4 + s
__device__ float g_psumsq[64 * 32];
__device__ unsigned g_ctr;            // monotonic ticket counter (never reset)

__device__ __forceinline__ unsigned long long add_f32x2(unsigned long long a,
                                                        unsigned long long b) {
    unsigned long long r;
    asm("add.rn.f32x2 %0, %1, %2;" : "=l"(r) : "l"(a), "l"(b));
    return r;
}

__global__ __launch_bounds__(256) void fused_kernel(
    const float* __restrict__ x, const float* __restrict__ W,
    const float* __restrict__ gamma, const float* __restrict__ beta,
    float* __restrict__ out)
{
    __shared__ __align__(16) float xs[32 * 16 * 16];   // 32KB
    __shared__ __align__(16) float nws[288 * 8];       // 9KB
    __shared__ float red[16][8];                       // warp partials
    __shared__ float2 scb[8];                          // per-oc {scale, bias}

    const int s   = blockIdx.x;   // spatial tile 0..3
    const int ocg = blockIdx.y;   // 0..7 (8 output channels each)
    const int n   = blockIdx.z;   // 0..7
    const int th  = (s >> 1) * 14;
    const int tw  = (s & 1) * 14;
    const int tid = threadIdx.x;
    const int wid = tid >> 5;
    const int lid = tid & 31;

    // ---- conv prologue (R1 verbatim) ----
    const float* xb = x + n * (32 * 28 * 28);
    #pragma unroll
    for (int i = tid; i < 32 * 256; i += 256) {
        int c = i >> 8, cell = i & 255;
        int r = cell >> 4, col = cell & 15;
        int gh = th - 1 + r, gw = tw - 1 + col;
        float v = 0.f;
        if ((unsigned)gh < 28u && (unsigned)gw < 28u)
            v = xb[c * 784 + gh * 28 + gw];
        xs[i] = v;
    }
    const float* Wb = W + ocg * (8 * 288);
    #pragma unroll
    for (int i = tid; i < 8 * 288; i += 256) {
        int o = i & 7, k = i >> 3;
        nws[k * 8 + o] = -Wb[o * 288 + k];
    }
    __syncthreads();

    // ---- conv mainloop (R1 verbatim) ----
    unsigned long long acc0 = 0ull, acc1 = 0ull, acc2 = 0ull, acc3 = 0ull;
    if (tid < 196) {
        const int ph = tid / 14;
        const int pw = tid - ph * 14;
        const float* xp = xs + ph * 16 + pw;
        const ulonglong2* wp = (const ulonglong2*)nws;

        #pragma unroll 1
        for (int c = 0; c < 32; ++c) {
            const float* xc = xp + c * 256;
            #pragma unroll
            for (int r = 0; r < 3; ++r) {
                #pragma unroll
                for (int q = 0; q < 3; ++q) {
                    float xv = xc[r * 16 + q];
                    unsigned long long xx;
                    asm("mov.b64 %0, {%1, %1};" : "=l"(xx) : "r"(__float_as_uint(xv)));
                    const ulonglong2* w4 = wp + (c * 9 + r * 3 + q) * 2;
                    ulonglong2 wA = w4[0];
                    ulonglong2 wB = w4[1];
                    unsigned long long d0 = add_f32x2(xx, wA.x) & 0x7FFFFFFF7FFFFFFFULL;
                    unsigned long long d1 = add_f32x2(xx, wA.y) & 0x7FFFFFFF7FFFFFFFULL;
                    unsigned long long d2 = add_f32x2(xx, wB.x) & 0x7FFFFFFF7FFFFFFFULL;
                    unsigned long long d3 = add_f32x2(xx, wB.y) & 0x7FFFFFFF7FFFFFFFULL;
                    acc0 = add_f32x2(acc0, d0);
                    acc1 = add_f32x2(acc1, d1);
                    acc2 = add_f32x2(acc2, d2);
                    acc3 = add_f32x2(acc3, d3);
                }
            }
        }
    }

    // ---- epilogue: unpack 8 positive abs-sums (val[j] = sum|x-w| for oc j) ----
    float val[8];
    {
        unsigned long long a[4] = {acc0, acc1, acc2, acc3};
        #pragma unroll
        for (int p = 0; p < 4; ++p) {
            val[2 * p]     = __uint_as_float((unsigned)(a[p] & 0xFFFFFFFFu));
            val[2 * p + 1] = __uint_as_float((unsigned)(a[p] >> 32));
        }
    }

    // Per-warp shfl reduce of sum (of -val) and sumsq (of val^2); zeros for tid>=196.
    float sv[8], qv[8];
    #pragma unroll
    for (int j = 0; j < 8; ++j) {
        float v = (tid < 196) ? val[j] : 0.f;
        sv[j] = -v;            // out value is -val
        qv[j] = v * v;
    }
    #pragma unroll
    for (int d = 16; d > 0; d >>= 1) {
        #pragma unroll
        for (int j = 0; j < 8; ++j) {
            sv[j] += __shfl_down_sync(0xFFFFFFFFu, sv[j], d);
            qv[j] += __shfl_down_sync(0xFFFFFFFFu, qv[j], d);
        }
    }
    if (lid == 0) {
        #pragma unroll
        for (int j = 0; j < 8; ++j) {
            red[j][wid]     = sv[j];
            red[j + 8][wid] = qv[j];
        }
    }
    __syncthreads();

    const int pidx = n * 4 + s;
    if (tid < 16) {
        float t = red[tid][0];
        #pragma unroll
        for (int u = 1; u < 8; ++u) t += red[tid][u];
        if (tid < 8) g_psum[(ocg * 8 + tid) * 32 + pidx] = t;
        else         g_psumsq[(ocg * 8 + (tid - 8)) * 32 + pidx] = t;
    }
    __syncthreads();

    // ---- replay-safe ticket barrier over the 256 co-resident blocks ----
    if (tid == 0) {
        __threadfence();
        unsigned arrival = atomicAdd(&g_ctr, 1u);
        unsigned target = ((arrival >> 8) + 1u) << 8;   // this launch's 256th ticket
        while ((int)(*(volatile unsigned*)&g_ctr - target) < 0) __nanosleep(64);
        __threadfence();
    }
    __syncthreads();

    // ---- per-channel stats: warp w folds oc (ocg*8+w)'s 32 partials ----
    {
        const int oc = ocg * 8 + wid;
        float ss = *(volatile float*)&g_psum[oc * 32 + lid];
        float qq = *(volatile float*)&g_psumsq[oc * 32 + lid];
        #pragma unroll
        for (int d = 16; d > 0; d >>= 1) {
            ss += __shfl_down_sync(0xFFFFFFFFu, ss, d);
            qq += __shfl_down_sync(0xFFFFFFFFu, qq, d);
        }
        if (lid == 0) {
            float mean = ss * (1.f / 6272.f);
            float var  = qq * (1.f / 6272.f) - mean * mean;
            float sc = gamma[oc] * rsqrtf(var + 1e-5f);
            scb[wid] = make_float2(sc, beta[oc] - mean * sc);
        }
    }
    __syncthreads();

    // ---- normalize in registers, single global write ----
    if (tid < 196) {
        const int ph = tid / 14;
        const int pw = tid - ph * 14;
        const int gh = th + ph, gw = tw + pw;
        float* ob = out + (n * 64 + ocg * 8) * 784 + gh * 28 + gw;
        #pragma unroll
        for (int j = 0; j < 8; ++j) {
            float2 c = scb[j];
            // y = (-val)*sc + bi
            ob[j * 784] = fmaf(val[j], -c.x, c.y);
        }
    }
}

extern "C" void kernel_launch(void* const* d_in, const int* in_sizes, int n_in,
                              void* d_out, int out_size) {
    const float* x     = (const float*)d_in[0];  // [8,32,28,28]
    const float* W     = (const float*)d_in[1];  // [64,32,3,3]
    const float* gamma = (const float*)d_in[2];  // [64]
    const float* beta  = (const float*)d_in[3];  // [64]
    float* out = (float*)d_out;                  // [8,64,28,28]

    dim3 g1(4, 8, 8);
    fused_kernel<<<g1, 256>>>(x, W, gamma, beta, out);
}